// round 7
// baseline (speedup 1.0000x reference)
#include <cuda_runtime.h>
#include <cuda_bf16.h>

// PyramidROIAlign, two-phase:
//  A) meta kernel: one thread per (roi,pos) computes bilinear metadata into a
//     static __device__ scratch array (L2-resident, 1.6MB max).
//  B) main kernel: one float4 output element per thread. Warp-uniform meta
//     loads (32 threads share a pp entry), 4 coalesced corner LDG.128, lerp,
//     linear streaming store. No smem, no syncs, minimal registers.

#define NPOS   49
#define C      256
#define CQ     64                       // float4 groups per (roi,pos)
#define MAX_PP (1024 * NPOS)            // up to 1024 ROIs

struct __align__(16) PPMeta {
    int   o00, o01, o10, o11;           // float offsets into the level map
    float wx, wy;
    int   lvl;                          // 2..5
    int   pad;
};

__device__ PPMeta g_meta[MAX_PP];

__global__ void meta_kernel(
    const float* __restrict__ boxes,    // [N,4]
    const float* __restrict__ meta,     // [93]
    int num_pp)
{
    const int pp = blockIdx.x * blockDim.x + threadIdx.x;
    if (pp >= num_pp) return;

    const int roi = pp / NPOS;
    const int pos = pp - roi * NPOS;

    const float y1 = boxes[roi * 4 + 0];
    const float x1 = boxes[roi * 4 + 1];
    const float y2 = boxes[roi * 4 + 2];
    const float x2 = boxes[roi * 4 + 3];
    const float h = y2 - y1;
    const float w = x2 - x1;

    // roi_level = clip(4 + round(log2(sqrt(h*w) / (224/sqrt(imgH*imgW)))), 2, 5)
    const float img_h = meta[4];
    const float img_w = meta[5];
    const float scale = 224.0f / sqrtf(img_h * img_w);
    const float lvl_f = log2f(sqrtf(h * w) / scale);
    int level = 4 + (int)rintf(lvl_f);          // round-half-even == jnp.round
    level = min(max(level, 2), 5);

    const int H = 1024 >> level;                // 256,128,64,32
    const int W = H;

    const int py = pos / 7;
    const int px = pos - py * 7;
    const float ys = (y1 + (float)py * (1.0f / 6.0f) * h) * (float)(H - 1);
    const float xs = (x1 + (float)px * (1.0f / 6.0f) * w) * (float)(W - 1);

    const float y0f = fminf(fmaxf(floorf(ys), 0.0f), (float)(H - 1));
    const float x0f = fminf(fmaxf(floorf(xs), 0.0f), (float)(W - 1));
    const int y0  = (int)y0f;
    const int x0  = (int)x0f;
    const int y1i = min(y0 + 1, H - 1);
    const int x1i = min(x0 + 1, W - 1);

    PPMeta m;
    m.o00 = (y0  * W + x0 ) * C;
    m.o01 = (y0  * W + x1i) * C;
    m.o10 = (y1i * W + x0 ) * C;
    m.o11 = (y1i * W + x1i) * C;
    m.wx  = xs - x0f;
    m.wy  = ys - y0f;
    m.lvl = level;
    m.pad = 0;
    g_meta[pp] = m;
}

__global__ __launch_bounds__(256) void pyramid_roi_align_kernel(
    const float* __restrict__ P2,       // [256,256,256]
    const float* __restrict__ P3,       // [128,128,256]
    const float* __restrict__ P4,       // [64,64,256]
    const float* __restrict__ P5,       // [32,32,256]
    float* __restrict__ out,            // [N,49,256]
    int num_tasks)                      // N*49*64
{
    const int g = blockIdx.x * 256 + threadIdx.x;
    if (g >= num_tasks) return;

    const int pp = g >> 6;              // (roi,pos) index — uniform across warp
    const int cg = (g & 63) << 2;       // channel offset in floats

    // warp-uniform metadata loads (broadcast: 1 wavefront each)
    const int4   offs = __ldg((const int4*)&g_meta[pp]);
    const float4 wv   = __ldg((const float4*)((const char*)&g_meta[pp] + 16));
    const float wx = wv.x;
    const float wy = wv.y;
    const int  lvl = __float_as_int(wv.z);

    const float* base = (lvl == 2) ? P2 : (lvl == 3) ? P3 : (lvl == 4) ? P4 : P5;

    // 4 independent coalesced 128-bit loads
    const float4 v00 = __ldg((const float4*)(base + offs.x + cg));
    const float4 v01 = __ldg((const float4*)(base + offs.y + cg));
    const float4 v10 = __ldg((const float4*)(base + offs.z + cg));
    const float4 v11 = __ldg((const float4*)(base + offs.w + cg));

    float4 r;
    float t, b;
    t = v00.x + (v01.x - v00.x) * wx;  b = v10.x + (v11.x - v10.x) * wx;  r.x = t + (b - t) * wy;
    t = v00.y + (v01.y - v00.y) * wx;  b = v10.y + (v11.y - v10.y) * wx;  r.y = t + (b - t) * wy;
    t = v00.z + (v01.z - v00.z) * wx;  b = v10.z + (v11.z - v10.z) * wx;  r.z = t + (b - t) * wy;
    t = v00.w + (v01.w - v00.w) * wx;  b = v10.w + (v11.w - v10.w) * wx;  r.w = t + (b - t) * wy;

    __stcs((float4*)(out + (long long)g * 4), r);   // pure linear store stream
}

extern "C" void kernel_launch(void* const* d_in, const int* in_sizes, int n_in,
                              void* d_out, int out_size) {
    const float* boxes = (const float*)d_in[0];   // ROIboxes [1,N,4]
    const float* meta  = (const float*)d_in[1];   // image_meta [1,93]
    const float* P2    = (const float*)d_in[2];
    const float* P3    = (const float*)d_in[3];
    const float* P4    = (const float*)d_in[4];
    const float* P5    = (const float*)d_in[5];
    float* out = (float*)d_out;

    const int N = in_sizes[0] / 4;
    const int num_pp = N * NPOS;
    const int num_tasks = num_pp * CQ;

    const int meta_blocks = (num_pp + 255) / 256;
    meta_kernel<<<meta_blocks, 256>>>(boxes, meta, num_pp);

    const int blocks = (num_tasks + 255) / 256;
    pyramid_roi_align_kernel<<<blocks, 256>>>(P2, P3, P4, P5, out, num_tasks);
}

// round 8
// speedup vs baseline: 1.0046x; 1.0046x over previous
#include <cuda_runtime.h>
#include <cuda_bf16.h>

// PyramidROIAlign: per-ROI blocks (L1 corner reuse + smem metadata = short
// load-dependency prefix), 224 threads/block so 3136 tasks divide exactly into
// 14 per thread (7 iterations x 2-task batch, MLP=8, no predication).
// Corner POINTERS precomputed in smem; stores are linear __stcs.

#define TPB    224
#define NPOS   49
#define C      256
#define NTASK  (NPOS * (C / 4))   // 3136 float4 tasks per ROI

__global__ __launch_bounds__(TPB) void pyramid_roi_align_kernel(
    const float* __restrict__ boxes,   // [N,4] y1,x1,y2,x2 normalized
    const float* __restrict__ meta,    // [93], meta[4],meta[5] = image H,W
    const float* __restrict__ P2,      // [256,256,256]
    const float* __restrict__ P3,      // [128,128,256]
    const float* __restrict__ P4,      // [64,64,256]
    const float* __restrict__ P5,      // [32,32,256]
    float* __restrict__ out)           // [N,49,256]
{
    const int n   = blockIdx.x;
    const int tid = threadIdx.x;

    __shared__ const float* s_p00[NPOS];
    __shared__ const float* s_p01[NPOS];
    __shared__ const float* s_p10[NPOS];
    __shared__ const float* s_p11[NPOS];
    __shared__ float2 s_w[NPOS];       // (wx, wy)

    if (tid < NPOS) {
        const float y1 = boxes[n * 4 + 0];
        const float x1 = boxes[n * 4 + 1];
        const float y2 = boxes[n * 4 + 2];
        const float x2 = boxes[n * 4 + 3];
        const float h = y2 - y1;
        const float w = x2 - x1;

        // roi_level = clip(4 + round(log2(sqrt(h*w) / (224/sqrt(imgH*imgW)))), 2, 5)
        const float img_h = meta[4];
        const float img_w = meta[5];
        const float scale = 224.0f / sqrtf(img_h * img_w);
        const float lvl_f = log2f(sqrtf(h * w) / scale);
        int level = 4 + (int)rintf(lvl_f);        // round-half-even == jnp.round
        level = min(max(level, 2), 5);

        const int H = 1024 >> level;              // 256,128,64,32
        const int W = H;
        const float* base = (level == 2) ? P2 : (level == 3) ? P3
                          : (level == 4) ? P4 : P5;

        const int py = tid / 7;
        const int px = tid - py * 7;
        const float ys = (y1 + (float)py * (1.0f / 6.0f) * h) * (float)(H - 1);
        const float xs = (x1 + (float)px * (1.0f / 6.0f) * w) * (float)(W - 1);

        const float y0f = fminf(fmaxf(floorf(ys), 0.0f), (float)(H - 1));
        const float x0f = fminf(fmaxf(floorf(xs), 0.0f), (float)(W - 1));
        const int y0  = (int)y0f;
        const int x0  = (int)x0f;
        const int y1i = min(y0 + 1, H - 1);
        const int x1i = min(x0 + 1, W - 1);

        s_w[tid]   = make_float2(xs - x0f, ys - y0f);
        s_p00[tid] = base + (y0  * W + x0 ) * C;
        s_p01[tid] = base + (y0  * W + x1i) * C;
        s_p10[tid] = base + (y1i * W + x0 ) * C;
        s_p11[tid] = base + (y1i * W + x1i) * C;
    }
    __syncthreads();

    float* __restrict__ out_base = out + (long long)n * (NTASK * 4);

    // 3136 tasks = 7 iterations x (2 tasks per thread, stride TPB).
    #pragma unroll 1
    for (int k = 0; k < 7; k++) {
        const int iA = tid + k * (2 * TPB);
        const int iB = iA + TPB;

        // ---- metadata from smem (short LDS prefix)
        const int posA = iA >> 6;
        const int cgA  = (iA & 63) << 2;
        const float2 wA = s_w[posA];
        const float* pA00 = s_p00[posA] + cgA;
        const float* pA01 = s_p01[posA] + cgA;
        const float* pA10 = s_p10[posA] + cgA;
        const float* pA11 = s_p11[posA] + cgA;

        const int posB = iB >> 6;
        const int cgB  = (iB & 63) << 2;
        const float2 wB = s_w[posB];
        const float* pB00 = s_p00[posB] + cgB;
        const float* pB01 = s_p01[posB] + cgB;
        const float* pB10 = s_p10[posB] + cgB;
        const float* pB11 = s_p11[posB] + cgB;

        // ---- 8 independent LDG.128
        const float4 a00 = __ldg((const float4*)pA00);
        const float4 a01 = __ldg((const float4*)pA01);
        const float4 a10 = __ldg((const float4*)pA10);
        const float4 a11 = __ldg((const float4*)pA11);
        const float4 b00 = __ldg((const float4*)pB00);
        const float4 b01 = __ldg((const float4*)pB01);
        const float4 b10 = __ldg((const float4*)pB10);
        const float4 b11 = __ldg((const float4*)pB11);

        // ---- compute + linear streaming stores
        float4 r;
        float t, bt;
        t = a00.x + (a01.x - a00.x) * wA.x;  bt = a10.x + (a11.x - a10.x) * wA.x;  r.x = t + (bt - t) * wA.y;
        t = a00.y + (a01.y - a00.y) * wA.x;  bt = a10.y + (a11.y - a10.y) * wA.x;  r.y = t + (bt - t) * wA.y;
        t = a00.z + (a01.z - a00.z) * wA.x;  bt = a10.z + (a11.z - a10.z) * wA.x;  r.z = t + (bt - t) * wA.y;
        t = a00.w + (a01.w - a00.w) * wA.x;  bt = a10.w + (a11.w - a10.w) * wA.x;  r.w = t + (bt - t) * wA.y;
        __stcs((float4*)(out_base + iA * 4), r);

        t = b00.x + (b01.x - b00.x) * wB.x;  bt = b10.x + (b11.x - b10.x) * wB.x;  r.x = t + (bt - t) * wB.y;
        t = b00.y + (b01.y - b00.y) * wB.x;  bt = b10.y + (b11.y - b10.y) * wB.x;  r.y = t + (bt - t) * wB.y;
        t = b00.z + (b01.z - b00.z) * wB.x;  bt = b10.z + (b11.z - b10.z) * wB.x;  r.z = t + (bt - t) * wB.y;
        t = b00.w + (b01.w - b00.w) * wB.x;  bt = b10.w + (b11.w - b10.w) * wB.x;  r.w = t + (bt - t) * wB.y;
        __stcs((float4*)(out_base + iB * 4), r);
    }
}

extern "C" void kernel_launch(void* const* d_in, const int* in_sizes, int n_in,
                              void* d_out, int out_size) {
    const float* boxes = (const float*)d_in[0];   // ROIboxes [1,N,4]
    const float* meta  = (const float*)d_in[1];   // image_meta [1,93]
    const float* P2    = (const float*)d_in[2];
    const float* P3    = (const float*)d_in[3];
    const float* P4    = (const float*)d_in[4];
    const float* P5    = (const float*)d_in[5];
    float* out = (float*)d_out;

    const int N = in_sizes[0] / 4;
    pyramid_roi_align_kernel<<<N, TPB>>>(boxes, meta, P2, P3, P4, P5, out);
}

// round 9
// speedup vs baseline: 1.0908x; 1.0858x over previous
#include <cuda_runtime.h>
#include <cuda_bf16.h>

// PyramidROIAlign: 2 blocks per ROI (finer residency granularity), 224 threads.
// Each block owns 1568 contiguous float4 tasks of its ROI (7 per thread =
// 3 double-iterations + 1 single, no predication). Metadata (corner pointers +
// weights) computed once per block into smem. 8 independent LDG.128 per double
// iteration; linear __stcs stores.

#define TPB    224
#define NPOS   49
#define C      256
#define NTASK  (NPOS * (C / 4))   // 3136 float4 tasks per ROI
#define HTASK  (NTASK / 2)        // 1568 per block

__global__ __launch_bounds__(TPB) void pyramid_roi_align_kernel(
    const float* __restrict__ boxes,   // [N,4] y1,x1,y2,x2 normalized
    const float* __restrict__ meta,    // [93], meta[4],meta[5] = image H,W
    const float* __restrict__ P2,      // [256,256,256]
    const float* __restrict__ P3,      // [128,128,256]
    const float* __restrict__ P4,      // [64,64,256]
    const float* __restrict__ P5,      // [32,32,256]
    float* __restrict__ out)           // [N,49,256]
{
    const int roi  = blockIdx.x >> 1;
    const int half = blockIdx.x & 1;
    const int tid  = threadIdx.x;

    __shared__ const float* s_p00[NPOS];
    __shared__ const float* s_p01[NPOS];
    __shared__ const float* s_p10[NPOS];
    __shared__ const float* s_p11[NPOS];
    __shared__ float2 s_w[NPOS];       // (wx, wy)

    if (tid < NPOS) {
        const float y1 = boxes[roi * 4 + 0];
        const float x1 = boxes[roi * 4 + 1];
        const float y2 = boxes[roi * 4 + 2];
        const float x2 = boxes[roi * 4 + 3];
        const float h = y2 - y1;
        const float w = x2 - x1;

        // roi_level = clip(4 + round(log2(sqrt(h*w) / (224/sqrt(imgH*imgW)))), 2, 5)
        const float img_h = meta[4];
        const float img_w = meta[5];
        const float scale = 224.0f / sqrtf(img_h * img_w);
        const float lvl_f = log2f(sqrtf(h * w) / scale);
        int level = 4 + (int)rintf(lvl_f);        // round-half-even == jnp.round
        level = min(max(level, 2), 5);

        const int H = 1024 >> level;              // 256,128,64,32
        const int W = H;
        const float* base = (level == 2) ? P2 : (level == 3) ? P3
                          : (level == 4) ? P4 : P5;

        const int py = tid / 7;
        const int px = tid - py * 7;
        const float ys = (y1 + (float)py * (1.0f / 6.0f) * h) * (float)(H - 1);
        const float xs = (x1 + (float)px * (1.0f / 6.0f) * w) * (float)(W - 1);

        const float y0f = fminf(fmaxf(floorf(ys), 0.0f), (float)(H - 1));
        const float x0f = fminf(fmaxf(floorf(xs), 0.0f), (float)(W - 1));
        const int y0  = (int)y0f;
        const int x0  = (int)x0f;
        const int y1i = min(y0 + 1, H - 1);
        const int x1i = min(x0 + 1, W - 1);

        s_w[tid]   = make_float2(xs - x0f, ys - y0f);
        s_p00[tid] = base + (y0  * W + x0 ) * C;
        s_p01[tid] = base + (y0  * W + x1i) * C;
        s_p10[tid] = base + (y1i * W + x0 ) * C;
        s_p11[tid] = base + (y1i * W + x1i) * C;
    }
    __syncthreads();

    float* __restrict__ out_base = out + (long long)roi * (NTASK * 4);
    const int t0 = half * HTASK;       // this block's first task within the ROI

    // 1568 tasks = 3 double-iterations (1344) + 1 single (224).
    #pragma unroll 1
    for (int k = 0; k < 3; k++) {
        const int iA = t0 + tid + k * (2 * TPB);
        const int iB = iA + TPB;

        const int posA = iA >> 6;
        const int cgA  = (iA & 63) << 2;
        const float2 wA = s_w[posA];
        const float* pA00 = s_p00[posA] + cgA;
        const float* pA01 = s_p01[posA] + cgA;
        const float* pA10 = s_p10[posA] + cgA;
        const float* pA11 = s_p11[posA] + cgA;

        const int posB = iB >> 6;
        const int cgB  = (iB & 63) << 2;
        const float2 wB = s_w[posB];
        const float* pB00 = s_p00[posB] + cgB;
        const float* pB01 = s_p01[posB] + cgB;
        const float* pB10 = s_p10[posB] + cgB;
        const float* pB11 = s_p11[posB] + cgB;

        const float4 a00 = __ldg((const float4*)pA00);
        const float4 a01 = __ldg((const float4*)pA01);
        const float4 a10 = __ldg((const float4*)pA10);
        const float4 a11 = __ldg((const float4*)pA11);
        const float4 b00 = __ldg((const float4*)pB00);
        const float4 b01 = __ldg((const float4*)pB01);
        const float4 b10 = __ldg((const float4*)pB10);
        const float4 b11 = __ldg((const float4*)pB11);

        float4 r;
        float t, bt;
        t = a00.x + (a01.x - a00.x) * wA.x;  bt = a10.x + (a11.x - a10.x) * wA.x;  r.x = t + (bt - t) * wA.y;
        t = a00.y + (a01.y - a00.y) * wA.x;  bt = a10.y + (a11.y - a10.y) * wA.x;  r.y = t + (bt - t) * wA.y;
        t = a00.z + (a01.z - a00.z) * wA.x;  bt = a10.z + (a11.z - a10.z) * wA.x;  r.z = t + (bt - t) * wA.y;
        t = a00.w + (a01.w - a00.w) * wA.x;  bt = a10.w + (a11.w - a10.w) * wA.x;  r.w = t + (bt - t) * wA.y;
        __stcs((float4*)(out_base + iA * 4), r);

        t = b00.x + (b01.x - b00.x) * wB.x;  bt = b10.x + (b11.x - b10.x) * wB.x;  r.x = t + (bt - t) * wB.y;
        t = b00.y + (b01.y - b00.y) * wB.x;  bt = b10.y + (b11.y - b10.y) * wB.x;  r.y = t + (bt - t) * wB.y;
        t = b00.z + (b01.z - b00.z) * wB.x;  bt = b10.z + (b11.z - b10.z) * wB.x;  r.z = t + (bt - t) * wB.y;
        t = b00.w + (b01.w - b00.w) * wB.x;  bt = b10.w + (b11.w - b10.w) * wB.x;  r.w = t + (bt - t) * wB.y;
        __stcs((float4*)(out_base + iB * 4), r);
    }

    // final single iteration
    {
        const int i  = t0 + tid + 6 * TPB;
        const int pos = i >> 6;
        const int cg  = (i & 63) << 2;
        const float2 wv = s_w[pos];
        const float4 v00 = __ldg((const float4*)(s_p00[pos] + cg));
        const float4 v01 = __ldg((const float4*)(s_p01[pos] + cg));
        const float4 v10 = __ldg((const float4*)(s_p10[pos] + cg));
        const float4 v11 = __ldg((const float4*)(s_p11[pos] + cg));

        float4 r;
        float t, bt;
        t = v00.x + (v01.x - v00.x) * wv.x;  bt = v10.x + (v11.x - v10.x) * wv.x;  r.x = t + (bt - t) * wv.y;
        t = v00.y + (v01.y - v00.y) * wv.x;  bt = v10.y + (v11.y - v10.y) * wv.x;  r.y = t + (bt - t) * wv.y;
        t = v00.z + (v01.z - v00.z) * wv.x;  bt = v10.z + (v11.z - v10.z) * wv.x;  r.z = t + (bt - t) * wv.y;
        t = v00.w + (v01.w - v00.w) * wv.x;  bt = v10.w + (v11.w - v10.w) * wv.x;  r.w = t + (bt - t) * wv.y;
        __stcs((float4*)(out_base + i * 4), r);
    }
}

extern "C" void kernel_launch(void* const* d_in, const int* in_sizes, int n_in,
                              void* d_out, int out_size) {
    const float* boxes = (const float*)d_in[0];   // ROIboxes [1,N,4]
    const float* meta  = (const float*)d_in[1];   // image_meta [1,93]
    const float* P2    = (const float*)d_in[2];
    const float* P3    = (const float*)d_in[3];
    const float* P4    = (const float*)d_in[4];
    const float* P5    = (const float*)d_in[5];
    float* out = (float*)d_out;

    const int N = in_sizes[0] / 4;
    pyramid_roi_align_kernel<<<N * 2, TPB>>>(boxes, meta, P2, P3, P4, P5, out);
}